// round 10
// baseline (speedup 1.0000x reference)
#include <cuda_runtime.h>
#include <cuda_fp16.h>
#include <math.h>
#include <stdint.h>

// ---------------- problem constants ----------------
constexpr int Bb   = 32;
constexpr int Nn   = 196;
constexpr int Cc   = 768;
constexpr int Hh   = 12;
constexpr int Ll   = 4;
constexpr int DFF  = 3072;
constexpr int HD   = Cc / Hh;          // 64
constexpr int ROWS = Bb * Nn;          // 6272
constexpr int NCAT = 2 * Nn;           // 392

// weight sizes per stream (elements)
constexpr int W_QKV = Cc * 3 * Cc;
constexpr int W_PRJ = Cc * Cc;
constexpr int W_FC1 = Cc * DFF;
constexpr int W_FC2 = DFF * Cc;
constexpr int W_ALL = W_QKV + W_PRJ + W_FC1 + W_FC2;
constexpr int W_HALF = W_ALL / 2;      // u32 per stream

// ---------------- scratch (static device memory; no allocation) ----------------
__device__ float    g_fused[Bb * Ll * Cc];
__device__ float    g_sw  [Bb * Ll * NCAT];
__device__ __half   g_h   [2 * ROWS * Cc];       // LN out (half, k-permuted)
__device__ float    g_qkv [2 * ROWS * 3 * Cc];   // qkv out (fp32)
__device__ __half   g_o   [2 * ROWS * Cc];       // attn out (half, k-permuted)
__device__ __half   g_mlp [2 * ROWS * DFF];      // gelu out (half, k-permuted)
__device__ uint32_t g_w   [W_ALL];               // 2 streams x W_HALF u32 (half2-packed)

// k-permutation within a 16-group: memory pos order = [2t,2t+1,2t+8,2t+9] for t=0..3.
__device__ __forceinline__ int permA(int c) {
    const int w = c & 15;
    return (c & ~15) | (((w & 7) >> 1) << 2) | ((w >> 3) << 1) | (w & 1);
}

// ============================================================================
// ALL weights -> half2-packed u32, n-permuted, ONE launch.
// ============================================================================
__global__ void round_w_all_kernel(const float* __restrict__ sq, const float* __restrict__ spj,
                                   const float* __restrict__ s1, const float* __restrict__ s2,
                                   const float* __restrict__ rq, const float* __restrict__ rpj,
                                   const float* __restrict__ r1, const float* __restrict__ r2,
                                   uint32_t* __restrict__ out)
{
    int i = blockIdx.x * blockDim.x + threadIdx.x;
    if (i >= W_ALL) return;
    const int s = i / W_HALF;
    int j = i - s * W_HALF;

    const float* in;
    int N;
    if (j < W_QKV / 2)                      { in = s ? rq : sq;   N = 3 * Cc; }
    else if (j < (W_QKV + W_PRJ) / 2)       { in = s ? rpj : spj; N = Cc;     j -= W_QKV / 2; }
    else if (j < (W_QKV + W_PRJ + W_FC1)/2) { in = s ? r1 : s1;   N = DFF;    j -= (W_QKV + W_PRJ) / 2; }
    else                                    { in = s ? r2 : s2;   N = Cc;     j -= (W_QKV + W_PRJ + W_FC1) / 2; }

    int kp = j / N, ps = j - kp * N;
    int p = ps & 31;
    int n = (ps & ~31) + ((p & 3) << 3) + (p >> 2);
    float lo = in[(size_t)(2 * kp) * N + n];
    float hi = in[(size_t)(2 * kp + 1) * N + n];
    __half2 h = __floats2half2_rn(lo, hi);
    out[i] = *(uint32_t*)&h;
}

// ============================================================================
// latent scores + softmax
// ============================================================================
__global__ void fl_scores_kernel(const float* __restrict__ x,
                                 const float* __restrict__ y,
                                 const float* __restrict__ lat,
                                 float* __restrict__ sw)
{
    const int b = blockIdx.x;
    const int tid = threadIdx.x, lane = tid & 31, w = tid >> 5;

    __shared__ float slat[Ll * Cc];
    __shared__ float s[Ll][NCAT];

    for (int i = tid; i < Ll * Cc; i += 256) slat[i] = lat[i];
    __syncthreads();

    const float scale = 0.03608439182435161f;

    for (int n = w; n < NCAT; n += 8) {
        const float* row = (n < Nn) ? x + (size_t)(b * Nn + n) * Cc
                                    : y + (size_t)(b * Nn + (n - Nn)) * Cc;
        float a0 = 0.f, a1 = 0.f, a2 = 0.f, a3 = 0.f;
        for (int c = lane; c < Cc; c += 32) {
            float v = row[c];
            a0 += slat[c] * v;
            a1 += slat[Cc + c] * v;
            a2 += slat[2 * Cc + c] * v;
            a3 += slat[3 * Cc + c] * v;
        }
        #pragma unroll
        for (int o = 16; o; o >>= 1) {
            a0 += __shfl_xor_sync(0xffffffffu, a0, o);
            a1 += __shfl_xor_sync(0xffffffffu, a1, o);
            a2 += __shfl_xor_sync(0xffffffffu, a2, o);
            a3 += __shfl_xor_sync(0xffffffffu, a3, o);
        }
        if (lane == 0) {
            s[0][n] = a0 * scale; s[1][n] = a1 * scale;
            s[2][n] = a2 * scale; s[3][n] = a3 * scale;
        }
    }
    __syncthreads();

    if (w < Ll) {
        float mx = -INFINITY;
        for (int n = lane; n < NCAT; n += 32) mx = fmaxf(mx, s[w][n]);
        #pragma unroll
        for (int o = 16; o; o >>= 1) mx = fmaxf(mx, __shfl_xor_sync(0xffffffffu, mx, o));
        float sum = 0.f;
        for (int n = lane; n < NCAT; n += 32) {
            float e = __expf(s[w][n] - mx);
            s[w][n] = e;
            sum += e;
        }
        #pragma unroll
        for (int o = 16; o; o >>= 1) sum += __shfl_xor_sync(0xffffffffu, sum, o);
        const float inv = 1.f / sum;
        float* swp = sw + (size_t)(b * Ll + w) * NCAT;
        for (int n = lane; n < NCAT; n += 32) swp[n] = s[w][n] * inv;
    }
}

// ============================================================================
// latent gather
// ============================================================================
__global__ void fl_gather_kernel(const float* __restrict__ x,
                                 const float* __restrict__ y,
                                 const float* __restrict__ sw,
                                 float* __restrict__ fused)
{
    const int b = blockIdx.x;
    const int col = blockIdx.y * 256 + threadIdx.x;
    const int tid = threadIdx.x;

    __shared__ float s[Ll][NCAT];
    for (int i = tid; i < Ll * NCAT; i += 256)
        s[i / NCAT][i % NCAT] = sw[(size_t)b * Ll * NCAT + i];
    __syncthreads();

    float a0 = 0.f, a1 = 0.f, a2 = 0.f, a3 = 0.f;
    const float* xb = x + (size_t)b * Nn * Cc + col;
    #pragma unroll 2
    for (int n = 0; n < Nn; n++) {
        float v = xb[(size_t)n * Cc];
        a0 += s[0][n] * v; a1 += s[1][n] * v; a2 += s[2][n] * v; a3 += s[3][n] * v;
    }
    const float* yb = y + (size_t)b * Nn * Cc + col;
    #pragma unroll 2
    for (int n = 0; n < Nn; n++) {
        float v = yb[(size_t)n * Cc];
        a0 += s[0][Nn + n] * v; a1 += s[1][Nn + n] * v;
        a2 += s[2][Nn + n] * v; a3 += s[3][Nn + n] * v;
    }
    float* fp = fused + (size_t)b * Ll * Cc + col;
    fp[0] = a0; fp[Cc] = a1; fp[2 * Cc] = a2; fp[3 * Cc] = a3;
}

// ============================================================================
// cross-attend residual
// ============================================================================
__global__ void cross_attend_kernel(const float* __restrict__ x,
                                    const float* __restrict__ y,
                                    const float* __restrict__ fused,
                                    const float* __restrict__ scale_a,
                                    const float* __restrict__ scale_v,
                                    float* __restrict__ outx,
                                    float* __restrict__ outy)
{
    const int row = blockIdx.x;
    const int b = row / Nn;
    const int tid = threadIdx.x;

    const float* in;
    float* out;
    float sc;
    if (blockIdx.y == 0) { in = x + (size_t)row * Cc; out = outx + (size_t)row * Cc; sc = *scale_a; }
    else                 { in = y + (size_t)row * Cc; out = outy + (size_t)row * Cc; sc = *scale_v; }

    const float* f = fused + (size_t)b * Ll * Cc;

    __shared__ float red[256];
    __shared__ float w4[Ll];

    float p0 = 0.f, p1 = 0.f, p2 = 0.f, p3 = 0.f;
    for (int c = tid; c < Cc; c += 256) {
        float v = in[c];
        p0 += v * f[c];
        p1 += v * f[Cc + c];
        p2 += v * f[2 * Cc + c];
        p3 += v * f[3 * Cc + c];
    }
    float ps[4] = {p0, p1, p2, p3};
    #pragma unroll
    for (int l = 0; l < Ll; l++) {
        red[tid] = ps[l];
        __syncthreads();
        for (int st = 128; st; st >>= 1) {
            if (tid < st) red[tid] += red[tid + st];
            __syncthreads();
        }
        if (tid == 0) w4[l] = red[0] * 0.03608439182435161f;
        __syncthreads();
    }
    if (tid == 0) {
        float mx = fmaxf(fmaxf(w4[0], w4[1]), fmaxf(w4[2], w4[3]));
        float e0 = __expf(w4[0] - mx), e1 = __expf(w4[1] - mx);
        float e2 = __expf(w4[2] - mx), e3 = __expf(w4[3] - mx);
        float inv = 1.f / (e0 + e1 + e2 + e3);
        w4[0] = e0 * inv; w4[1] = e1 * inv; w4[2] = e2 * inv; w4[3] = e3 * inv;
    }
    __syncthreads();

    const float a0 = w4[0], a1 = w4[1], a2 = w4[2], a3 = w4[3];
    for (int c = tid; c < Cc; c += 256) {
        float r = a0 * f[c] + a1 * f[Cc + c] + a2 * f[2 * Cc + c] + a3 * f[3 * Cc + c];
        out[c] = in[c] + sc * r;
    }
}

// ============================================================================
// LayerNorm (batched over 2 streams); output = half, k-permuted (feeds GEMM A)
// ============================================================================
__global__ void ln_kernel(const float* __restrict__ inb,
                          const float* __restrict__ g0, const float* __restrict__ b0,
                          const float* __restrict__ g1, const float* __restrict__ b1,
                          __half* __restrict__ outb)
{
    const int z = blockIdx.y;
    const int row = blockIdx.x;
    const int tid = threadIdx.x;
    const float* g   = z ? g1 : g0;
    const float* bta = z ? b1 : b0;
    const float* ip = inb  + ((size_t)z * ROWS + row) * Cc;
    __half*      op = outb + ((size_t)z * ROWS + row) * Cc;

    __shared__ float red[256];
    __shared__ float s_mean, s_rstd;

    float v0 = ip[tid], v1 = ip[tid + 256], v2 = ip[tid + 512];
    float sum = v0 + v1 + v2;
    red[tid] = sum;
    __syncthreads();
    for (int st = 128; st; st >>= 1) { if (tid < st) red[tid] += red[tid + st]; __syncthreads(); }
    if (tid == 0) s_mean = red[0] * (1.f / Cc);
    __syncthreads();
    const float mean = s_mean;

    float d0 = v0 - mean, d1 = v1 - mean, d2 = v2 - mean;
    red[tid] = d0 * d0 + d1 * d1 + d2 * d2;
    __syncthreads();
    for (int st = 128; st; st >>= 1) { if (tid < st) red[tid] += red[tid + st]; __syncthreads(); }
    if (tid == 0) s_rstd = rsqrtf(red[0] * (1.f / Cc) + 1e-6f);
    __syncthreads();
    const float rstd = s_rstd;

    op[permA(tid)]       = __float2half_rn(d0 * rstd * g[tid]       + bta[tid]);
    op[permA(tid + 256)] = __float2half_rn(d1 * rstd * g[tid + 256] + bta[tid + 256]);
    op[permA(tid + 512)] = __float2half_rn(d2 * rstd * g[tid + 512] + bta[tid + 512]);
}

// ============================================================================
// FP16 tensor-core GEMM: 128x128 block, 4 warps (2x2) at 64x64, m16n8k16,
// fp32 accumulate, 4-stage cp.async, 2 CTAs/SM (128 threads).
// A smem: [128][16] halves (32B rows), k pre-permuted -> LDS.64 = (a0,a2).
// B smem: [8][136] u32 half2 k-pairs, n pre-permuted -> LDS.128 = 4 n-tiles.
// EPI: 0 = bias (f32 out), 1 = bias+gelu (half out, k-permuted), 2 = bias+residual.
// ============================================================================
constexpr int LDBW = 136;
constexpr int A_STG_H = 128 * 16;
constexpr int B_STG_W = 8 * LDBW;
constexpr int A_STG_BYTES = A_STG_H * 2;          // 4096
constexpr int B_STG_BYTES = B_STG_W * 4;          // 4352
constexpr int STAGES = 4;
constexpr int GEMM_SMEM = STAGES * (A_STG_BYTES + B_STG_BYTES);  // 33792

__device__ __forceinline__ void cp_async16(uint32_t s, const void* g) {
    asm volatile("cp.async.ca.shared.global [%0], [%1], 16;" :: "r"(s), "l"(g));
}
__device__ __forceinline__ void cp_commit() {
    asm volatile("cp.async.commit_group;");
}
template<int N>
__device__ __forceinline__ void cp_wait() {
    asm volatile("cp.async.wait_group %0;" :: "n"(N));
}

__device__ __forceinline__ void mma_f16(float* d, uint32_t a0, uint32_t a1,
                                        uint32_t a2, uint32_t a3,
                                        uint32_t b0, uint32_t b1) {
    asm volatile(
        "mma.sync.aligned.m16n8k16.row.col.f32.f16.f16.f32 "
        "{%0,%1,%2,%3}, {%4,%5,%6,%7}, {%8,%9}, {%0,%1,%2,%3};"
        : "+f"(d[0]), "+f"(d[1]), "+f"(d[2]), "+f"(d[3])
        : "r"(a0), "r"(a1), "r"(a2), "r"(a3), "r"(b0), "r"(b1));
}

template<int EPI>
__global__ __launch_bounds__(128, 2)
void h16_gemm_kernel(const __half* __restrict__ Abase, size_t strideA,
                     const uint32_t* __restrict__ W0, const uint32_t* __restrict__ W1,
                     const float* __restrict__ bias0, const float* __restrict__ bias1,
                     const float* __restrict__ resbase,
                     void* __restrict__ Cbase, size_t strideC,
                     int M, int N, int K)
{
    extern __shared__ char smem[];
    __half*   Ash = (__half*)smem;
    uint32_t* Bsh = (uint32_t*)(smem + STAGES * A_STG_BYTES);

    const int z = blockIdx.z;
    const __half* A     = Abase + (size_t)z * strideA;
    const uint32_t* Wm  = z ? W1 : W0;
    const float* bias   = z ? bias1 : bias0;
    const float* res    = (EPI == 2) ? resbase + (size_t)z * strideC : nullptr;
    float*  Cf = (float*)Cbase + (size_t)z * strideC;
    __half* Ch = (__half*)Cbase + (size_t)z * strideC;

    const int tid  = threadIdx.x;
    const int lane = tid & 31;
    const int w    = tid >> 5;
    const int wm   = w >> 1;          // 0..1 : 64-row slab
    const int wn   = w & 1;           // 0..1 : 64-col slab
    const int gid  = lane >> 2;
    const int tig  = lane & 3;

    const int bm = blockIdx.y * 128;
    const int bn = blockIdx.x * 128;

    float acc[4][8][4];
    #pragma unroll
    for (int i = 0; i < 4; i++)
        #pragma unroll
        for (int j = 0; j < 8; j++)
            #pragma unroll
            for (int q = 0; q < 4; q++) acc[i][j][q] = 0.f;

    // loaders (128 threads): A row t = 32B -> 2 cp.async; B row t>>4, chunk t&15 -> 2 cp.async
    const int arow = tid;                    // 0..127
    const int brow = tid >> 4;               // 0..7
    const int bchk = (tid & 15) * 8;         // u32 col base

    const __half* Ap = A + (size_t)(bm + arow) * K;
    const uint32_t* Bp = Wm + (size_t)brow * N + bn + bchk;

    const uint32_t sA = (uint32_t)__cvta_generic_to_shared(&Ash[arow * 16]);
    const uint32_t sB = (uint32_t)__cvta_generic_to_shared(&Bsh[brow * LDBW + bchk]);

    const int KT = K / 16;

    auto load_tile = [&](int kt, int stg) {
        const __half* a = Ap + kt * 16;
        const uint32_t* b = Bp + (size_t)kt * 8 * N;
        const uint32_t sa = sA + stg * A_STG_BYTES;
        const uint32_t sb = sB + stg * B_STG_BYTES;
        cp_async16(sa, a);
        cp_async16(sa + 16, a + 8);
        cp_async16(sb, b);
        cp_async16(sb + 16, b + 4);
        cp_commit();
    };

    load_tile(0, 0);
    load_tile(1, 1);
    load_tile(2, 2);
    cp_wait<2>();
    __syncthreads();

    int buf = 0;
    for (int kt = 0; kt < KT; kt++) {
        if (kt + 3 < KT) {
            int s = buf + 3; if (s >= STAGES) s -= STAGES;
            load_tile(kt + 3, s);
        }

        const __half* Aw = Ash + buf * A_STG_H + (wm * 64 + gid) * 16 + tig * 4;
        const uint32_t* Bw = Bsh + buf * B_STG_W + wn * 64 + gid * 4;

        // B fragments: 4 LDS.128 (two 32-blocks x k-low/k-high)
        uint4 b00 = *(const uint4*)(Bw + tig * LDBW);            // j 0..3, b0
        uint4 b01 = *(const uint4*)(Bw + (tig + 4) * LDBW);      // j 0..3, b1
        uint4 b10 = *(const uint4*)(Bw + tig * LDBW + 32);       // j 4..7, b0
        uint4 b11 = *(const uint4*)(Bw + (tig + 4) * LDBW + 32); // j 4..7, b1

        #pragma unroll
        for (int i = 0; i < 4; i++) {
            uint2 aLo = *(const uint2*)(Aw + i * 256);
            uint2 aHi = *(const uint2*)(Aw + i * 256 + 128);
            mma_f16(acc[i][0], aLo.x, aHi.x, aLo.y, aHi.y, b00.x, b01.x);
            mma_f16(acc[i][1], aLo.x, aHi.x, aLo.y, aHi.y, b00.y, b01.y);
            mma_f16(acc[i][2], aLo.x, aHi.x, aLo.y, aHi.y, b00.z, b01.z);
            mma_f16(acc[i][3], aLo.x, aHi.x, aLo.y, aHi.y, b00.w, b01.w);
            mma_f16(acc[i][4], aLo.x, aHi.x, aLo.y, aHi.y, b10.x, b11.x);
            mma_f16(acc[i][5], aLo.x, aHi.x, aLo.y, aHi.y, b10.y, b11.y);
            mma_f16(acc[i][6], aLo.x, aHi.x, aLo.y, aHi.y, b10.z, b11.z);
            mma_f16(acc[i][7], aLo.x, aHi.x, aLo.y, aHi.y, b10.w, b11.w);
        }

        if (kt + 1 < KT) {
            cp_wait<2>();
            __syncthreads();
            buf = (buf + 1 < STAGES) ? buf + 1 : 0;
        }
    }

    #pragma unroll
    for (int i = 0; i < 4; i++) {
        const int r0 = bm + wm * 64 + i * 16 + gid;
        #pragma unroll
        for (int j = 0; j < 8; j++) {
            const int c = bn + wn * 64 + (j >> 2) * 32 + (j & 3) * 8 + tig * 2;
            const float b0 = bias[c], b1 = bias[c + 1];

            float v0 = acc[i][j][0] + b0;
            float v1 = acc[i][j][1] + b1;
            float v2 = acc[i][j][2] + b0;
            float v3 = acc[i][j][3] + b1;
            if (EPI == 1) {
                v0 = v0 * 0.5f * (1.f + erff(v0 * 0.70710678118654752f));
                v1 = v1 * 0.5f * (1.f + erff(v1 * 0.70710678118654752f));
                v2 = v2 * 0.5f * (1.f + erff(v2 * 0.70710678118654752f));
                v3 = v3 * 0.5f * (1.f + erff(v3 * 0.70710678118654752f));
                const int pa = permA(c);
                *(__half2*)&Ch[(size_t)r0 * N + pa]       = __floats2half2_rn(v0, v1);
                *(__half2*)&Ch[(size_t)(r0 + 8) * N + pa] = __floats2half2_rn(v2, v3);
            } else {
                if (EPI == 2) {
                    const float* r = res + (size_t)r0 * N + c;
                    v0 += r[0]; v1 += r[1];
                    const float* r2 = res + (size_t)(r0 + 8) * N + c;
                    v2 += r2[0]; v3 += r2[1];
                }
                *(float2*)&Cf[(size_t)r0 * N + c]       = make_float2(v0, v1);
                *(float2*)&Cf[(size_t)(r0 + 8) * N + c] = make_float2(v2, v3);
            }
        }
    }
}

// ============================================================================
// Attention: one block per (b, head); batched over streams via blockIdx.y.
// K stride-68 float4 rows, V transposed stride-204, q in registers.
// output = half, k-permuted (feeds proj GEMM A)
// ============================================================================
constexpr int KST = HD + 4;                      // 68
constexpr int VST = Nn + 8;                      // 204
constexpr int ATTN_SMEM = (Nn * KST + HD * VST + 8 * Nn + 8 * HD) * 4;

__global__ void attn_kernel(const float* __restrict__ qkvb_, __half* __restrict__ ob_)
{
    extern __shared__ float sm[];
    float* Ks = sm;
    float* Vt = Ks + Nn * KST;
    float* S  = Vt + HD * VST;
    float* Qs = S + 8 * Nn;

    const int z = blockIdx.y;
    const int bh = blockIdx.x;
    const int b = bh / Hh, hh = bh % Hh;
    const int tid = threadIdx.x, lane = tid & 31, w = tid >> 5;

    const float* qkvb = qkvb_ + (size_t)z * ROWS * 3 * Cc + (size_t)b * Nn * (3 * Cc);
    __half* o = ob_ + (size_t)z * ROWS * Cc;

    for (int idx = tid; idx < Nn * HD; idx += 256) {
        const int n = idx >> 6, d = idx & 63;
        const float* rp = qkvb + (size_t)n * (3 * Cc) + hh * HD + d;
        Ks[n * KST + d] = rp[Cc];
        Vt[d * VST + n] = rp[2 * Cc];
    }
    __syncthreads();

    float* Sw = S + w * Nn;
    float* Qw = Qs + w * HD;

    for (int r = w; r < Nn; r += 8) {
        const float* qp = qkvb + (size_t)r * (3 * Cc) + hh * HD;
        Qw[lane] = qp[lane];
        Qw[lane + 32] = qp[lane + 32];
        __syncwarp();

        float q[HD];
        #pragma unroll
        for (int d = 0; d < HD; d++) q[d] = Qw[d];

        float mx = -INFINITY;
        for (int k = lane; k < Nn; k += 32) {
            const float* kr = &Ks[k * KST];
            float acc = 0.f;
            #pragma unroll
            for (int c = 0; c < HD / 4; c++) {
                float4 kk = *(const float4*)(kr + c * 4);
                acc = fmaf(q[4 * c],     kk.x, acc);
                acc = fmaf(q[4 * c + 1], kk.y, acc);
                acc = fmaf(q[4 * c + 2], kk.z, acc);
                acc = fmaf(q[4 * c + 3], kk.w, acc);
            }
            acc *= 0.125f;
            Sw[k] = acc;
            mx = fmaxf(mx, acc);
        }
        #pragma unroll
        for (int off = 16; off; off >>= 1) mx = fmaxf(mx, __shfl_xor_sync(0xffffffffu, mx, off));

        float sum = 0.f;
        for (int k = lane; k < Nn; k += 32) {
            float e = __expf(Sw[k] - mx);
            Sw[k] = e;
            sum += e;
        }
        #pragma unroll
        for (int off = 16; off; off >>= 1) sum += __shfl_xor_sync(0xffffffffu, sum, off);
        const float inv = 1.f / sum;
        __syncwarp();

        const float* v0r = &Vt[lane * VST];
        const float* v1r = &Vt[(lane + 32) * VST];
        float a0 = 0.f, a1 = 0.f;
        #pragma unroll 7
        for (int k0 = 0; k0 < Nn; k0 += 4) {
            float4 p  = *(const float4*)&Sw[k0];
            float4 u0 = *(const float4*)(v0r + k0);
            float4 u1 = *(const float4*)(v1r + k0);
            a0 += p.x * u0.x + p.y * u0.y + p.z * u0.z + p.w * u0.w;
            a1 += p.x * u1.x + p.y * u1.y + p.z * u1.z + p.w * u1.w;
        }
        __half* op = o + (size_t)(b * Nn + r) * Cc;
        const int c0 = hh * HD + lane;
        op[permA(c0)]      = __float2half_rn(a0 * inv);
        op[permA(c0 + 32)] = __float2half_rn(a1 * inv);
        __syncwarp();
    }
}

// ============================================================================
// host launcher
// ============================================================================
extern "C" void kernel_launch(void* const* d_in, const int* in_sizes, int n_in,
                              void* d_out, int out_size)
{
    const float* x        = (const float*)d_in[0];
    const float* y        = (const float*)d_in[1];
    const float* latents  = (const float*)d_in[2];
    const float* scale_a  = (const float*)d_in[3];
    const float* scale_v  = (const float*)d_in[4];

    const float* sp[12];
    const float* rp[12];
    for (int i = 0; i < 12; i++) { sp[i] = (const float*)d_in[5 + i]; rp[i] = (const float*)d_in[17 + i]; }

    float* outx = (float*)d_out;

    float *fused, *swbuf, *qkvbuf;
    __half *hbuf, *obuf, *mlpbuf;
    uint32_t* wbuf;
    cudaGetSymbolAddress((void**)&fused,  g_fused);
    cudaGetSymbolAddress((void**)&swbuf,  g_sw);
    cudaGetSymbolAddress((void**)&hbuf,   g_h);
    cudaGetSymbolAddress((void**)&qkvbuf, g_qkv);
    cudaGetSymbolAddress((void**)&obuf,   g_o);
    cudaGetSymbolAddress((void**)&mlpbuf, g_mlp);
    cudaGetSymbolAddress((void**)&wbuf,   g_w);

    cudaFuncSetAttribute(attn_kernel, cudaFuncAttributeMaxDynamicSharedMemorySize, ATTN_SMEM);

    const size_t sC   = (size_t)ROWS * Cc;
    const size_t sQKV = (size_t)ROWS * 3 * Cc;
    const size_t sMLP = (size_t)ROWS * DFF;

    uint32_t* wq[2]; uint32_t* wp[2]; uint32_t* w1[2]; uint32_t* w2[2];
    for (int s = 0; s < 2; s++) {
        uint32_t* base = wbuf + (size_t)s * W_HALF;
        wq[s] = base;
        wp[s] = base + W_QKV / 2;
        w1[s] = base + (W_QKV + W_PRJ) / 2;
        w2[s] = base + (W_QKV + W_PRJ + W_FC1) / 2;
    }

    // launch order keeps ncu (-s 5 -c 1) capture on launch #6 = qkv GEMM
    round_w_all_kernel<<<(W_ALL + 255) / 256, 256>>>(
        sp[2], sp[4], sp[8], sp[10], rp[2], rp[4], rp[8], rp[10], wbuf);

    fl_scores_kernel<<<Bb, 256>>>(x, y, latents, swbuf);
    fl_gather_kernel<<<dim3(Bb, 3), 256>>>(x, y, swbuf, fused);

    cross_attend_kernel<<<dim3(ROWS, 2), 256>>>(x, y, fused, scale_a, scale_v,
                                                outx, outx + sC);

    ln_kernel<<<dim3(ROWS, 2), 256>>>(outx, sp[0], sp[1], rp[0], rp[1], hbuf);
    h16_gemm_kernel<0><<<dim3(3 * Cc / 128, ROWS / 128, 2), 128, GEMM_SMEM>>>(
        hbuf, sC, wq[0], wq[1], sp[3], rp[3], nullptr, qkvbuf, sQKV,
        ROWS, 3 * Cc, Cc);

    attn_kernel<<<dim3(Bb * Hh, 2), 256, ATTN_SMEM>>>(qkvbuf, obuf);

    h16_gemm_kernel<2><<<dim3(Cc / 128, ROWS / 128, 2), 128, GEMM_SMEM>>>(
        obuf, sC, wp[0], wp[1], sp[5], rp[5], outx, outx, sC,
        ROWS, Cc, Cc);

    ln_kernel<<<dim3(ROWS, 2), 256>>>(outx, sp[6], sp[7], rp[6], rp[7], hbuf);
    h16_gemm_kernel<1><<<dim3(DFF / 128, ROWS / 128, 2), 128, GEMM_SMEM>>>(
        hbuf, sC, w1[0], w1[1], sp[9], rp[9], nullptr, mlpbuf, sMLP,
        ROWS, DFF, Cc);
    h16_gemm_kernel<2><<<dim3(Cc / 128, ROWS / 128, 2), 128, GEMM_SMEM>>>(
        mlpbuf, sMLP, w2[0], w2[1], sp[11], rp[11], outx, outx, sC,
        ROWS, Cc, DFF);
}

// round 12
// speedup vs baseline: 1.0843x; 1.0843x over previous
#include <cuda_runtime.h>
#include <cuda_fp16.h>
#include <math.h>
#include <stdint.h>

// ---------------- problem constants ----------------
constexpr int Bb   = 32;
constexpr int Nn   = 196;
constexpr int Cc   = 768;
constexpr int Hh   = 12;
constexpr int Ll   = 4;
constexpr int DFF  = 3072;
constexpr int HD   = Cc / Hh;          // 64
constexpr int ROWS = Bb * Nn;          // 6272
constexpr int NCAT = 2 * Nn;           // 392

// weight sizes per stream (elements)
constexpr int W_QKV = Cc * 3 * Cc;
constexpr int W_PRJ = Cc * Cc;
constexpr int W_FC1 = Cc * DFF;
constexpr int W_FC2 = DFF * Cc;
constexpr int W_ALL = W_QKV + W_PRJ + W_FC1 + W_FC2;
constexpr int W_HALF = W_ALL / 2;      // u32 per stream

// ---------------- scratch (static device memory; no allocation) ----------------
__device__ float    g_fused[Bb * Ll * Cc];
__device__ __half   g_h   [2 * ROWS * Cc];       // LN out (half, k-permuted)
__device__ float    g_qkv [2 * ROWS * 3 * Cc];   // qkv out (fp32)
__device__ __half   g_o   [2 * ROWS * Cc];       // attn out (half, k-permuted)
__device__ __half   g_mlp [2 * ROWS * DFF];      // gelu out (half, k-permuted)
__device__ uint32_t g_w   [W_ALL];               // 2 streams x W_HALF u32 (half2-packed)

// k-permutation within a 16-group: memory pos order = [2t,2t+1,2t+8,2t+9] for t=0..3.
__device__ __forceinline__ int permA(int c) {
    const int w = c & 15;
    return (c & ~15) | (((w & 7) >> 1) << 2) | ((w >> 3) << 1) | (w & 1);
}

// ============================================================================
// ALL weights -> half2-packed u32, n-permuted, ONE launch.
// ============================================================================
__global__ void round_w_all_kernel(const float* __restrict__ sq, const float* __restrict__ spj,
                                   const float* __restrict__ s1, const float* __restrict__ s2,
                                   const float* __restrict__ rq, const float* __restrict__ rpj,
                                   const float* __restrict__ r1, const float* __restrict__ r2,
                                   uint32_t* __restrict__ out)
{
    int i = blockIdx.x * blockDim.x + threadIdx.x;
    if (i >= W_ALL) return;
    const int s = i / W_HALF;
    int j = i - s * W_HALF;

    const float* in;
    int N;
    if (j < W_QKV / 2)                      { in = s ? rq : sq;   N = 3 * Cc; }
    else if (j < (W_QKV + W_PRJ) / 2)       { in = s ? rpj : spj; N = Cc;     j -= W_QKV / 2; }
    else if (j < (W_QKV + W_PRJ + W_FC1)/2) { in = s ? r1 : s1;   N = DFF;    j -= (W_QKV + W_PRJ) / 2; }
    else                                    { in = s ? r2 : s2;   N = Cc;     j -= (W_QKV + W_PRJ + W_FC1) / 2; }

    int kp = j / N, ps = j - kp * N;
    int p = ps & 31;
    int n = (ps & ~31) + ((p & 3) << 3) + (p >> 2);
    float lo = in[(size_t)(2 * kp) * N + n];
    float hi = in[(size_t)(2 * kp + 1) * N + n];
    __half2 h = __floats2half2_rn(lo, hi);
    out[i] = *(uint32_t*)&h;
}

// ============================================================================
// fused latents = sdpa(latents, concat(x,y), concat(x,y), C^-0.5)
// one block per batch (R7-verified version)
// ============================================================================
__global__ void fuse_latents_kernel(const float* __restrict__ x,
                                    const float* __restrict__ y,
                                    const float* __restrict__ lat,
                                    float* __restrict__ fused)
{
    const int b = blockIdx.x;
    const int tid = threadIdx.x, lane = tid & 31, w = tid >> 5;

    __shared__ float slat[Ll * Cc];
    __shared__ float s[Ll][NCAT];

    for (int i = tid; i < Ll * Cc; i += 256) slat[i] = lat[i];
    __syncthreads();

    const float scale = 0.03608439182435161f;  // 1/sqrt(768)

    for (int n = w; n < NCAT; n += 8) {
        const float* row = (n < Nn) ? x + (size_t)(b * Nn + n) * Cc
                                    : y + (size_t)(b * Nn + (n - Nn)) * Cc;
        float a0 = 0.f, a1 = 0.f, a2 = 0.f, a3 = 0.f;
        for (int c = lane; c < Cc; c += 32) {
            float v = row[c];
            a0 += slat[c] * v;
            a1 += slat[Cc + c] * v;
            a2 += slat[2 * Cc + c] * v;
            a3 += slat[3 * Cc + c] * v;
        }
        #pragma unroll
        for (int o = 16; o; o >>= 1) {
            a0 += __shfl_xor_sync(0xffffffffu, a0, o);
            a1 += __shfl_xor_sync(0xffffffffu, a1, o);
            a2 += __shfl_xor_sync(0xffffffffu, a2, o);
            a3 += __shfl_xor_sync(0xffffffffu, a3, o);
        }
        if (lane == 0) {
            s[0][n] = a0 * scale; s[1][n] = a1 * scale;
            s[2][n] = a2 * scale; s[3][n] = a3 * scale;
        }
    }
    __syncthreads();

    if (w < Ll) {
        float mx = -INFINITY;
        for (int n = lane; n < NCAT; n += 32) mx = fmaxf(mx, s[w][n]);
        #pragma unroll
        for (int o = 16; o; o >>= 1) mx = fmaxf(mx, __shfl_xor_sync(0xffffffffu, mx, o));
        float sum = 0.f;
        for (int n = lane; n < NCAT; n += 32) {
            float e = __expf(s[w][n] - mx);
            s[w][n] = e;
            sum += e;
        }
        #pragma unroll
        for (int o = 16; o; o >>= 1) sum += __shfl_xor_sync(0xffffffffu, sum, o);
        const float inv = 1.f / sum;
        for (int n = lane; n < NCAT; n += 32) s[w][n] *= inv;
    }
    __syncthreads();

    float acc[Ll][3];
    #pragma unroll
    for (int l = 0; l < Ll; l++) { acc[l][0] = acc[l][1] = acc[l][2] = 0.f; }

    const float* xb = x + (size_t)b * Nn * Cc;
    const float* yb = y + (size_t)b * Nn * Cc;
    #pragma unroll 2
    for (int n = 0; n < Nn; n++) {
        const float* row = xb + (size_t)n * Cc;
        float v0 = row[tid], v1 = row[tid + 256], v2 = row[tid + 512];
        #pragma unroll
        for (int l = 0; l < Ll; l++) {
            float sl = s[l][n];
            acc[l][0] += sl * v0; acc[l][1] += sl * v1; acc[l][2] += sl * v2;
        }
    }
    #pragma unroll 2
    for (int n = 0; n < Nn; n++) {
        const float* row = yb + (size_t)n * Cc;
        float v0 = row[tid], v1 = row[tid + 256], v2 = row[tid + 512];
        #pragma unroll
        for (int l = 0; l < Ll; l++) {
            float sl = s[l][Nn + n];
            acc[l][0] += sl * v0; acc[l][1] += sl * v1; acc[l][2] += sl * v2;
        }
    }
    #pragma unroll
    for (int l = 0; l < Ll; l++) {
        float* fp = fused + (size_t)(b * Ll + l) * Cc;
        fp[tid] = acc[l][0]; fp[tid + 256] = acc[l][1]; fp[tid + 512] = acc[l][2];
    }
}

// ============================================================================
// FUSED: out = in + scale * sdpa(in, fused, fused, C^-0.5);  h = LN1(out) half
// warp-shuffle reductions; one block per (row, stream)
// ============================================================================
__global__ void cross_attend_ln_kernel(const float* __restrict__ x,
                                       const float* __restrict__ y,
                                       const float* __restrict__ fused,
                                       const float* __restrict__ scale_a,
                                       const float* __restrict__ scale_v,
                                       const float* __restrict__ g0, const float* __restrict__ b0,
                                       const float* __restrict__ g1, const float* __restrict__ b1,
                                       float* __restrict__ outb,
                                       __half* __restrict__ hb)
{
    const int row = blockIdx.x;
    const int b = row / Nn;
    const int z = blockIdx.y;
    const int tid = threadIdx.x, lane = tid & 31, w = tid >> 5;

    const float* in = (z ? y : x) + (size_t)row * Cc;
    float* out = outb + ((size_t)z * ROWS + row) * Cc;
    __half* hout = hb + ((size_t)z * ROWS + row) * Cc;
    const float sc = z ? *scale_v : *scale_a;
    const float* g   = z ? g1 : g0;
    const float* bta = z ? b1 : b0;
    const float* f = fused + (size_t)b * Ll * Cc;

    __shared__ float red[32];
    __shared__ float w4[Ll];
    __shared__ float sred[8];

    const float v0 = in[tid], v1 = in[tid + 256], v2 = in[tid + 512];

    // 4 latent dots via registers + warp shuffle
    float p[4];
    #pragma unroll
    for (int l = 0; l < Ll; l++) {
        const float* fl = f + l * Cc;
        p[l] = v0 * fl[tid] + v1 * fl[tid + 256] + v2 * fl[tid + 512];
    }
    #pragma unroll
    for (int o = 16; o; o >>= 1) {
        p[0] += __shfl_xor_sync(0xffffffffu, p[0], o);
        p[1] += __shfl_xor_sync(0xffffffffu, p[1], o);
        p[2] += __shfl_xor_sync(0xffffffffu, p[2], o);
        p[3] += __shfl_xor_sync(0xffffffffu, p[3], o);
    }
    if (lane == 0) {
        red[w * 4 + 0] = p[0]; red[w * 4 + 1] = p[1];
        red[w * 4 + 2] = p[2]; red[w * 4 + 3] = p[3];
    }
    __syncthreads();
    if (tid == 0) {
        float t[4] = {0.f, 0.f, 0.f, 0.f};
        #pragma unroll
        for (int i = 0; i < 8; i++) {
            t[0] += red[i * 4]; t[1] += red[i * 4 + 1];
            t[2] += red[i * 4 + 2]; t[3] += red[i * 4 + 3];
        }
        const float scale = 0.03608439182435161f;
        float s0 = t[0] * scale, s1 = t[1] * scale, s2 = t[2] * scale, s3 = t[3] * scale;
        float mx = fmaxf(fmaxf(s0, s1), fmaxf(s2, s3));
        float e0 = __expf(s0 - mx), e1 = __expf(s1 - mx);
        float e2 = __expf(s2 - mx), e3 = __expf(s3 - mx);
        float inv = 1.f / (e0 + e1 + e2 + e3);
        w4[0] = e0 * inv; w4[1] = e1 * inv; w4[2] = e2 * inv; w4[3] = e3 * inv;
    }
    __syncthreads();

    const float a0 = w4[0], a1 = w4[1], a2 = w4[2], a3 = w4[3];
    float o0 = v0 + sc * (a0 * f[tid]       + a1 * f[Cc + tid]       + a2 * f[2 * Cc + tid]       + a3 * f[3 * Cc + tid]);
    float o1 = v1 + sc * (a0 * f[tid + 256] + a1 * f[Cc + tid + 256] + a2 * f[2 * Cc + tid + 256] + a3 * f[3 * Cc + tid + 256]);
    float o2 = v2 + sc * (a0 * f[tid + 512] + a1 * f[Cc + tid + 512] + a2 * f[2 * Cc + tid + 512] + a3 * f[3 * Cc + tid + 512]);
    out[tid] = o0; out[tid + 256] = o1; out[tid + 512] = o2;

    // ---- LN on (o0,o1,o2) ----
    float sum = o0 + o1 + o2;
    #pragma unroll
    for (int o = 16; o; o >>= 1) sum += __shfl_xor_sync(0xffffffffu, sum, o);
    if (lane == 0) sred[w] = sum;
    __syncthreads();
    float mean = 0.f;
    #pragma unroll
    for (int i = 0; i < 8; i++) mean += sred[i];
    mean *= (1.f / Cc);
    __syncthreads();

    float d0 = o0 - mean, d1 = o1 - mean, d2 = o2 - mean;
    float var = d0 * d0 + d1 * d1 + d2 * d2;
    #pragma unroll
    for (int o = 16; o; o >>= 1) var += __shfl_xor_sync(0xffffffffu, var, o);
    if (lane == 0) sred[w] = var;
    __syncthreads();
    float vs = 0.f;
    #pragma unroll
    for (int i = 0; i < 8; i++) vs += sred[i];
    const float rstd = rsqrtf(vs * (1.f / Cc) + 1e-6f);

    hout[permA(tid)]       = __float2half_rn(d0 * rstd * g[tid]       + bta[tid]);
    hout[permA(tid + 256)] = __float2half_rn(d1 * rstd * g[tid + 256] + bta[tid + 256]);
    hout[permA(tid + 512)] = __float2half_rn(d2 * rstd * g[tid + 512] + bta[tid + 512]);
}

// ============================================================================
// LayerNorm (LN2), shuffle reductions; output = half, k-permuted
// ============================================================================
__global__ void ln_kernel(const float* __restrict__ inb,
                          const float* __restrict__ g0, const float* __restrict__ b0,
                          const float* __restrict__ g1, const float* __restrict__ b1,
                          __half* __restrict__ outb)
{
    const int z = blockIdx.y;
    const int row = blockIdx.x;
    const int tid = threadIdx.x, lane = tid & 31, w = tid >> 5;
    const float* g   = z ? g1 : g0;
    const float* bta = z ? b1 : b0;
    const float* ip = inb  + ((size_t)z * ROWS + row) * Cc;
    __half*      op = outb + ((size_t)z * ROWS + row) * Cc;

    __shared__ float sred[8];

    float v0 = ip[tid], v1 = ip[tid + 256], v2 = ip[tid + 512];
    float sum = v0 + v1 + v2;
    #pragma unroll
    for (int o = 16; o; o >>= 1) sum += __shfl_xor_sync(0xffffffffu, sum, o);
    if (lane == 0) sred[w] = sum;
    __syncthreads();
    float mean = 0.f;
    #pragma unroll
    for (int i = 0; i < 8; i++) mean += sred[i];
    mean *= (1.f / Cc);
    __syncthreads();

    float d0 = v0 - mean, d1 = v1 - mean, d2 = v2 - mean;
    float var = d0 * d0 + d1 * d1 + d2 * d2;
    #pragma unroll
    for (int o = 16; o; o >>= 1) var += __shfl_xor_sync(0xffffffffu, var, o);
    if (lane == 0) sred[w] = var;
    __syncthreads();
    float vs = 0.f;
    #pragma unroll
    for (int i = 0; i < 8; i++) vs += sred[i];
    const float rstd = rsqrtf(vs * (1.f / Cc) + 1e-6f);

    op[permA(tid)]       = __float2half_rn(d0 * rstd * g[tid]       + bta[tid]);
    op[permA(tid + 256)] = __float2half_rn(d1 * rstd * g[tid + 256] + bta[tid + 256]);
    op[permA(tid + 512)] = __float2half_rn(d2 * rstd * g[tid + 512] + bta[tid + 512]);
}

// ============================================================================
// FP16 tensor-core GEMM (R8 shape): 128x128 block, 8 warps (2x4) at 64x32,
// m16n8k16, fp32 acc. Stage = 2 k-tiles (K-step 32), 3 stages, ONE sync per
// 32-k. 2 CTAs/SM. A sub-tile [128][16] k-permuted; B sub-tile [8][136] u32
// n-permuted. EPI: 0 = bias f32, 1 = bias+gelu half permA, 2 = bias+residual.
// ============================================================================
constexpr int LDBW = 136;
constexpr int A_TILE_H = 128 * 16;                // halves per k-tile
constexpr int B_TILE_W = 8 * LDBW;                // u32 per k-tile
constexpr int A_TILE_BYTES = A_TILE_H * 2;        // 4096
constexpr int B_TILE_BYTES = B_TILE_W * 4;        // 4352
constexpr int A_STG_BYTES = 2 * A_TILE_BYTES;     // 8192
constexpr int B_STG_BYTES = 2 * B_TILE_BYTES;     // 8704
constexpr int STAGES = 3;
constexpr int GEMM_SMEM = STAGES * (A_STG_BYTES + B_STG_BYTES);  // 50688

__device__ __forceinline__ void cp_async16(uint32_t s, const void* g) {
    asm volatile("cp.async.ca.shared.global [%0], [%1], 16;" :: "r"(s), "l"(g));
}
__device__ __forceinline__ void cp_commit() {
    asm volatile("cp.async.commit_group;");
}
template<int N>
__device__ __forceinline__ void cp_wait() {
    asm volatile("cp.async.wait_group %0;" :: "n"(N));
}

__device__ __forceinline__ void mma_f16(float* d, uint32_t a0, uint32_t a1,
                                        uint32_t a2, uint32_t a3,
                                        uint32_t b0, uint32_t b1) {
    asm volatile(
        "mma.sync.aligned.m16n8k16.row.col.f32.f16.f16.f32 "
        "{%0,%1,%2,%3}, {%4,%5,%6,%7}, {%8,%9}, {%0,%1,%2,%3};"
        : "+f"(d[0]), "+f"(d[1]), "+f"(d[2]), "+f"(d[3])
        : "r"(a0), "r"(a1), "r"(a2), "r"(a3), "r"(b0), "r"(b1));
}

template<int EPI>
__global__ __launch_bounds__(256, 2)
void h16_gemm_kernel(const __half* __restrict__ Abase, size_t strideA,
                     const uint32_t* __restrict__ W0, const uint32_t* __restrict__ W1,
                     const float* __restrict__ bias0, const float* __restrict__ bias1,
                     const float* __restrict__ resbase,
                     void* __restrict__ Cbase, size_t strideC,
                     int M, int N, int K)
{
    extern __shared__ char smem[];
    char* Ar = smem;
    char* Br = smem + STAGES * A_STG_BYTES;

    const int z = blockIdx.z;
    const __half* A     = Abase + (size_t)z * strideA;
    const uint32_t* Wm  = z ? W1 : W0;
    const float* bias   = z ? bias1 : bias0;
    const float* res    = (EPI == 2) ? resbase + (size_t)z * strideC : nullptr;
    float*  Cf = (float*)Cbase + (size_t)z * strideC;
    __half* Ch = (__half*)Cbase + (size_t)z * strideC;

    const int tid  = threadIdx.x;
    const int lane = tid & 31;
    const int w    = tid >> 5;
    const int wm   = w >> 2;
    const int wn   = w & 3;
    const int gid  = lane >> 2;
    const int tig  = lane & 3;

    const int bm = blockIdx.y * 128;
    const int bn = blockIdx.x * 128;

    float acc[4][4][4];
    #pragma unroll
    for (int i = 0; i < 4; i++)
        #pragma unroll
        for (int j = 0; j < 4; j++)
            #pragma unroll
            for (int q = 0; q < 4; q++) acc[i][j][q] = 0.f;

    const int arow = tid >> 1;
    const int achk = tid & 1;
    const int bkp  = tid >> 5;
    const int bcol = (tid & 31) * 4;

    const __half* Ap = A + (size_t)(bm + arow) * K + achk * 8;
    const uint32_t* Bp = Wm + (size_t)bkp * N + bn + bcol;

    const uint32_t sA = (uint32_t)__cvta_generic_to_shared(Ar) + arow * 32 + achk * 16;
    const uint32_t sB = (uint32_t)__cvta_generic_to_shared(Br) + (bkp * LDBW + bcol) * 4;

    const int KT2 = K / 32;

    auto load_stage = [&](int k2, int stg) {
        #pragma unroll
        for (int sub = 0; sub < 2; sub++) {
            const int kt = k2 * 2 + sub;
            cp_async16(sA + stg * A_STG_BYTES + sub * A_TILE_BYTES, Ap + kt * 16);
            cp_async16(sB + stg * B_STG_BYTES + sub * B_TILE_BYTES, Bp + (size_t)kt * 8 * N);
        }
        cp_commit();
    };

    load_stage(0, 0);
    load_stage(1, 1);
    cp_wait<1>();
    __syncthreads();

    int buf = 0;
    for (int k2 = 0; k2 < KT2; k2++) {
        if (k2 + 2 < KT2) {
            int s = buf + 2; if (s >= STAGES) s -= STAGES;
            load_stage(k2 + 2, s);
        }

        #pragma unroll
        for (int sub = 0; sub < 2; sub++) {
            const __half* Aw = (const __half*)(Ar + buf * A_STG_BYTES + sub * A_TILE_BYTES)
                               + (wm * 64 + gid) * 16 + tig * 4;
            const uint32_t* Bw = (const uint32_t*)(Br + buf * B_STG_BYTES + sub * B_TILE_BYTES)
                                 + wn * 32 + gid * 4;

            uint4 bq0 = *(const uint4*)(Bw + tig * LDBW);
            uint4 bq1 = *(const uint4*)(Bw + (tig + 4) * LDBW);

            #pragma unroll
            for (int i = 0; i < 4; i++) {
                uint2 aLo = *(const uint2*)(Aw + i * 256);
                uint2 aHi = *(const uint2*)(Aw + i * 256 + 128);
                mma_f16(acc[i][0], aLo.x, aHi.x, aLo.y, aHi.y, bq0.x, bq1.x);
                mma_f16(acc[i][1], aLo.x, aHi.x, aLo.y, aHi.y, bq0.y, bq1.y);
                mma_f16(acc[i][2], aLo.x, aHi.x, aLo.y, aHi.y, bq0.z, bq1.z);
                mma_f16(acc[i][3], aLo.x, aHi.x, aLo.y, aHi.y, bq0.w, bq1.w);
            }
        }

        if (k2 + 1 < KT2) {
            cp_wait<1>();
            __syncthreads();
            buf = (buf + 1 < STAGES) ? buf + 1 : 0;
        }
    }

    #pragma unroll
    for (int i = 0; i < 4; i++) {
        const int r0 = bm + wm * 64 + i * 16 + gid;
        #pragma unroll
        for (int j = 0; j < 4; j++) {
            const int c = bn + wn * 32 + j * 8 + tig * 2;
            const float b0 = bias[c], b1 = bias[c + 1];

            float v0 = acc[i][j][0] + b0;
            float v1 = acc[i][j][1] + b1;
            float v2 = acc[i][j][2] + b0;
            float v3 = acc[i][j][3] + b1;
            if (EPI == 1) {
                v0 = v0 * 0.5f * (1.f + erff(v0 * 0.70710678118654752f));
                v1 = v1 * 0.5f * (1.f + erff(v1 * 0.70710678118654752f));
                v2 = v2 * 0.5f * (1.f + erff(v2 * 0.70710678118654752f));
                v3 = v3 * 0.5f * (1.f + erff(v3 * 0.70710678118654752f));
                const int pa = permA(c);
                *(__half2*)&Ch[(size_t)r0 * N + pa]       = __floats2half2_rn(v0, v1);
                *(__half2*)&Ch[(size_t)(r0 + 8) * N + pa] = __floats2half2_rn(v2, v3);
            } else {
                if (EPI == 2) {
                    const float* r = res + (size_t)r0 * N + c;
                    v0 += r[0]; v1 += r[1];
                    const float* r2 = res + (size_t)(r0 + 8) * N + c;
                    v2 += r2[0]; v3 += r2[1];
                }
                *(float2*)&Cf[(size_t)r0 * N + c]       = make_float2(v0, v1);
                *(float2*)&Cf[(size_t)(r0 + 8) * N + c] = make_float2(v2, v3);
            }
        }
    }
}

// ============================================================================
// Attention (R8 version): K stride-68 float4, V transposed stride-204,
// q in registers; output half, k-permuted
// ============================================================================
constexpr int KST = HD + 4;                      // 68
constexpr int VST = Nn + 8;                      // 204
constexpr int ATTN_SMEM = (Nn * KST + HD * VST + 8 * Nn + 8 * HD) * 4;

__global__ void attn_kernel(const float* __restrict__ qkvb_, __half* __restrict__ ob_)
{
    extern __shared__ float sm[];
    float* Ks = sm;
    float* Vt = Ks + Nn * KST;
    float* S  = Vt + HD * VST;
    float* Qs = S + 8 * Nn;

    const int z = blockIdx.y;
    const int bh = blockIdx.x;
    const int b = bh / Hh, hh = bh % Hh;
    const int tid = threadIdx.x, lane = tid & 31, w = tid >> 5;

    const float* qkvb = qkvb_ + (size_t)z * ROWS * 3 * Cc + (size_t)b * Nn * (3 * Cc);
    __half* o = ob_ + (size_t)z * ROWS * Cc;

    for (int idx = tid; idx < Nn * HD; idx += 256) {
        const int n = idx >> 6, d = idx & 63;
        const float* rp = qkvb + (size_t)n * (3 * Cc) + hh * HD + d;
        Ks[n * KST + d] = rp[Cc];
        Vt[d * VST + n] = rp[2 * Cc];
    }
    __syncthreads();

    float* Sw = S + w * Nn;
    float* Qw = Qs + w * HD;

    for (int r = w; r < Nn; r += 8) {
        const float* qp = qkvb + (size_t)r * (3 * Cc) + hh * HD;
        Qw[lane] = qp[lane];
        Qw[lane + 32] = qp[lane + 32];
        __syncwarp();

        float q[HD];
        #pragma unroll
        for (int d = 0; d < HD; d++) q[d] = Qw[d];

        float mx = -INFINITY;
        for (int k = lane; k < Nn; k += 32) {
            const float* kr = &Ks[k * KST];
            float acc = 0.f;
            #pragma unroll
            for (int c = 0; c < HD / 4; c++) {
                float4 kk = *(const float4*)(kr + c * 4);
                acc = fmaf(q[4 * c],     kk.x, acc);
                acc = fmaf(q[4 * c + 1], kk.y, acc);
                acc = fmaf(q[4 * c + 2], kk.z, acc);
                acc = fmaf(q[4 * c + 3], kk.w, acc);
            }
            acc *= 0.125f;
            Sw[k] = acc;
            mx = fmaxf(mx, acc);
        }
        #pragma unroll
        for (int off = 16; off; off >>= 1) mx = fmaxf(mx, __shfl_xor_sync(0xffffffffu, mx, off));

        float sum = 0.f;
        for (int k = lane; k < Nn; k += 32) {
            float e = __expf(Sw[k] - mx);
            Sw[k] = e;
            sum += e;
        }
        #pragma unroll
        for (int off = 16; off; off >>= 1) sum += __shfl_xor_sync(0xffffffffu, sum, off);
        const float inv = 1.f / sum;
        __syncwarp();

        const float* v0r = &Vt[lane * VST];
        const float* v1r = &Vt[(lane + 32) * VST];
        float a0 = 0.f, a1 = 0.f;
        #pragma unroll 7
        for (int k0 = 0; k0 < Nn; k0 += 4) {
            float4 p  = *(const float4*)&Sw[k0];
            float4 u0 = *(const float4*)(v0r + k0);
            float4 u1 = *(const float4*)(v1r + k0);
            a0 += p.x * u0.x + p.y * u0.y + p.z * u0.z + p.w * u0.w;
            a1 += p.x * u1.x + p.y * u1.y + p.z * u1.z + p.w * u1.w;
        }
        __half* op = o + (size_t)(b * Nn + r) * Cc;
        const int c0 = hh * HD + lane;
        op[permA(c0)]      = __float2half_rn(a0 * inv);
        op[permA(c0 + 32)] = __float2half_rn(a1 * inv);
        __syncwarp();
    }
}

// ============================================================================
// host launcher
// ============================================================================
extern "C" void kernel_launch(void* const* d_in, const int* in_sizes, int n_in,
                              void* d_out, int out_size)
{
    const float* x        = (const float*)d_in[0];
    const float* y        = (const float*)d_in[1];
    const float* latents  = (const float*)d_in[2];
    const float* scale_a  = (const float*)d_in[3];
    const float* scale_v  = (const float*)d_in[4];

    const float* sp[12];
    const float* rp[12];
    for (int i = 0; i < 12; i++) { sp[i] = (const float*)d_in[5 + i]; rp[i] = (const float*)d_in[17 + i]; }

    float* outx = (float*)d_out;

    float *fused, *qkvbuf;
    __half *hbuf, *obuf, *mlpbuf;
    uint32_t* wbuf;
    cudaGetSymbolAddress((void**)&fused,  g_fused);
    cudaGetSymbolAddress((void**)&hbuf,   g_h);
    cudaGetSymbolAddress((void**)&qkvbuf, g_qkv);
    cudaGetSymbolAddress((void**)&obuf,   g_o);
    cudaGetSymbolAddress((void**)&mlpbuf, g_mlp);
    cudaGetSymbolAddress((void**)&wbuf,   g_w);

    // GEMM_SMEM (50688 B) exceeds the 48 KB default — opt-in is REQUIRED.
    cudaFuncSetAttribute(attn_kernel, cudaFuncAttributeMaxDynamicSharedMemorySize, ATTN_SMEM);
    cudaFuncSetAttribute(h16_gemm_kernel<0>, cudaFuncAttributeMaxDynamicSharedMemorySize, GEMM_SMEM);
    cudaFuncSetAttribute(h16_gemm_kernel<1>, cudaFuncAttributeMaxDynamicSharedMemorySize, GEMM_SMEM);
    cudaFuncSetAttribute(h16_gemm_kernel<2>, cudaFuncAttributeMaxDynamicSharedMemorySize, GEMM_SMEM);

    const size_t sC   = (size_t)ROWS * Cc;
    const size_t sQKV = (size_t)ROWS * 3 * Cc;
    const size_t sMLP = (size_t)ROWS * DFF;

    uint32_t* wq[2]; uint32_t* wp[2]; uint32_t* w1[2]; uint32_t* w2[2];
    for (int s = 0; s < 2; s++) {
        uint32_t* base = wbuf + (size_t)s * W_HALF;
        wq[s] = base;
        wp[s] = base + W_QKV / 2;
        w1[s] = base + (W_QKV + W_PRJ) / 2;
        w2[s] = base + (W_QKV + W_PRJ + W_FC1) / 2;
    }

    // launch order: #4 = qkv GEMM (ncu captures the 4th launch)
    // 1: weights
    round_w_all_kernel<<<(W_ALL + 255) / 256, 256>>>(
        sp[2], sp[4], sp[8], sp[10], rp[2], rp[4], rp[8], rp[10], wbuf);

    // 2: latent bottleneck (merged)
    fuse_latents_kernel<<<Bb, 256>>>(x, y, latents, fused);

    // 3: cross-attend residual + LN1 (fused)
    cross_attend_ln_kernel<<<dim3(ROWS, 2), 256>>>(
        x, y, fused, scale_a, scale_v,
        sp[0], sp[1], rp[0], rp[1], outx, hbuf);

    // 4: qkv GEMM  <-- ncu capture
    h16_gemm_kernel<0><<<dim3(3 * Cc / 128, ROWS / 128, 2), 256, GEMM_SMEM>>>(
        hbuf, sC, wq[0], wq[1], sp[3], rp[3], nullptr, qkvbuf, sQKV,
        ROWS, 3 * Cc, Cc);

    // 5: attention
    attn_kernel<<<dim3(Bb * Hh, 2), 256, ATTN_SMEM>>>(qkvbuf, obuf);

    // 6: proj + residual
    h16_gemm_kernel<2><<<dim3(Cc / 128, ROWS / 128, 2), 256, GEMM_SMEM>>>(
        obuf, sC, wp[0], wp[1], sp[5], rp[5], outx, outx, sC,
        ROWS, Cc, Cc);

    // 7: LN2
    ln_kernel<<<dim3(ROWS, 2), 256>>>(outx, sp[6], sp[7], rp[6], rp[7], hbuf);

    // 8: fc1 + gelu
    h16_gemm_kernel<1><<<dim3(DFF / 128, ROWS / 128, 2), 256, GEMM_SMEM>>>(
        hbuf, sC, w1[0], w1[1], sp[9], rp[9], nullptr, mlpbuf, sMLP,
        ROWS, DFF, Cc);

    // 9: fc2 + residual
    h16_gemm_kernel<2><<<dim3(Cc / 128, ROWS / 128, 2), 256, GEMM_SMEM>>>(
        mlpbuf, sMLP, w2[0], w2[1], sp[11], rp[11], outx, outx, sC,
        ROWS, Cc, DFF);
}